// round 4
// baseline (speedup 1.0000x reference)
#include <cuda_runtime.h>
#include <cstdint>

#define NATOMS 50000
#define NEDGES 800000
#define FDIM   64

// scratch
__device__ float g_x[NATOMS * 3 * FDIM];   // x = MLP(q), [N,192]
__device__ int   g_cnt[NATOMS];            // histogram of idx_i
__device__ int   g_off[NATOMS];            // exclusive offsets
__device__ int   g_cur[NATOMS];            // scatter cursors
__device__ int2  g_ej[NEDGES];             // (edge id, idx_j) sorted by idx_i

// ---- packed f32x2 helpers -------------------------------------------------
#define PK2(d, lo, hi) \
    asm("mov.b64 %0, {%1, %2};" : "=l"(d) : "r"(__float_as_uint(lo)), "r"(__float_as_uint(hi)))
#define UPK2(lo, hi, d) do { unsigned _ulo, _uhi; \
    asm("mov.b64 {%0, %1}, %2;" : "=r"(_ulo), "=r"(_uhi) : "l"(d)); \
    lo = __uint_as_float(_ulo); hi = __uint_as_float(_uhi); } while (0)
#define FMA2(acc, a, b) \
    asm("fma.rn.f32x2 %0, %1, %2, %0;" : "+l"(acc) : "l"(a), "l"(b))

#define HSTRIDE 68   // padded row stride (float4-aligned slots)

// ---------------------------------------------------------------------------
// Kernel A: per-atom MLP  x = W2 * silu(W1*q + b1) + b2
// ---------------------------------------------------------------------------
__global__ __launch_bounds__(256) void painn_mlp_kernel(
    const float* __restrict__ q,
    const float* __restrict__ W1, const float* __restrict__ b1,
    const float* __restrict__ W2, const float* __restrict__ b2,
    float* __restrict__ xout)
{
    __shared__ float sH[128 * HSTRIDE];
    __shared__ float sB2[192];

    const int t = threadIdx.x;
    const int atom0 = blockIdx.x * 128;
    const int tx = t & 15;
    const int ty = t >> 4;

    for (int k = t; k < 128 * 16; k += 256) {
        int a = k >> 4, c4 = k & 15;
        int ga = atom0 + a;
        float4 v = (ga < NATOMS) ? __ldg((const float4*)q + (size_t)ga * 16 + c4)
                                 : make_float4(0.f, 0.f, 0.f, 0.f);
        *(float4*)&sH[a * HSTRIDE + c4 * 4] = v;
    }
    if (t < 192) sB2[t] = b2[t];
    __syncthreads();

    // phase 1: h = silu(q*W1 + b1)
    unsigned long long acc1[8][2];
#pragma unroll
    for (int r = 0; r < 8; r++) { acc1[r][0] = 0ull; acc1[r][1] = 0ull; }

    const float4* W1v = (const float4*)W1;
#pragma unroll 4
    for (int k = 0; k < 64; k++) {
        float4 w = __ldg(&W1v[k * 16 + tx]);
        unsigned long long wp0, wp1;
        PK2(wp0, w.x, w.y);
        PK2(wp1, w.z, w.w);
#pragma unroll
        for (int r = 0; r < 8; r++) {
            float h = sH[(ty * 8 + r) * HSTRIDE + k];
            unsigned long long hp;
            PK2(hp, h, h);
            FMA2(acc1[r][0], hp, wp0);
            FMA2(acc1[r][1], hp, wp1);
        }
    }
    __syncthreads();

    {
        float b0 = __ldg(&b1[tx * 4 + 0]);
        float bb1 = __ldg(&b1[tx * 4 + 1]);
        float b2v = __ldg(&b1[tx * 4 + 2]);
        float b3 = __ldg(&b1[tx * 4 + 3]);
#pragma unroll
        for (int r = 0; r < 8; r++) {
            float v0, v1, v2, v3;
            UPK2(v0, v1, acc1[r][0]);
            UPK2(v2, v3, acc1[r][1]);
            v0 += b0; v1 += bb1; v2 += b2v; v3 += b3;
            v0 = v0 / (1.0f + __expf(-v0));
            v1 = v1 / (1.0f + __expf(-v1));
            v2 = v2 / (1.0f + __expf(-v2));
            v3 = v3 / (1.0f + __expf(-v3));
            float* row = &sH[(ty * 8 + r) * HSTRIDE + tx * 4];
            row[0] = v0; row[1] = v1; row[2] = v2; row[3] = v3;
        }
    }
    __syncthreads();

    // phase 2: x = h*W2 + b2
    unsigned long long a2[8][6];
#pragma unroll
    for (int r = 0; r < 8; r++)
#pragma unroll
        for (int c = 0; c < 6; c++) a2[r][c] = 0ull;

    const float4* W2v = (const float4*)W2;
    const int oc4 = tx * 3;
#pragma unroll 2
    for (int k = 0; k < 64; k++) {
        float4 wa = __ldg(&W2v[k * 48 + oc4 + 0]);
        float4 wb = __ldg(&W2v[k * 48 + oc4 + 1]);
        float4 wc = __ldg(&W2v[k * 48 + oc4 + 2]);
        unsigned long long w0, w1, w2, w3, w4, w5;
        PK2(w0, wa.x, wa.y); PK2(w1, wa.z, wa.w);
        PK2(w2, wb.x, wb.y); PK2(w3, wb.z, wb.w);
        PK2(w4, wc.x, wc.y); PK2(w5, wc.z, wc.w);
#pragma unroll
        for (int r = 0; r < 8; r++) {
            float h = sH[(ty * 8 + r) * HSTRIDE + k];
            unsigned long long hp;
            PK2(hp, h, h);
            FMA2(a2[r][0], hp, w0);
            FMA2(a2[r][1], hp, w1);
            FMA2(a2[r][2], hp, w2);
            FMA2(a2[r][3], hp, w3);
            FMA2(a2[r][4], hp, w4);
            FMA2(a2[r][5], hp, w5);
        }
    }

    const int ocol = tx * 12;
#pragma unroll
    for (int r = 0; r < 8; r++) {
        int atom = atom0 + ty * 8 + r;
        if (atom < NATOMS) {
            float v[12];
#pragma unroll
            for (int c = 0; c < 6; c++) UPK2(v[2 * c], v[2 * c + 1], a2[r][c]);
            float* dst = &xout[(size_t)atom * 192 + ocol];
#pragma unroll
            for (int c = 0; c < 12; c += 4) {
                float4 o;
                o.x = v[c + 0] + sB2[ocol + c + 0];
                o.y = v[c + 1] + sB2[ocol + c + 1];
                o.z = v[c + 2] + sB2[ocol + c + 2];
                o.w = v[c + 3] + sB2[ocol + c + 3];
                *(float4*)(dst + c) = o;
            }
        }
    }
}

// ---------------------------------------------------------------------------
// Sort-by-i prep kernels
// ---------------------------------------------------------------------------
__global__ __launch_bounds__(256) void zero_cnt_kernel() {
    int i = blockIdx.x * blockDim.x + threadIdx.x;
    if (i < NATOMS) { g_cnt[i] = 0; g_cur[i] = 0; }
}

__global__ __launch_bounds__(256) void hist_kernel(const int* __restrict__ idx_i) {
    int e = blockIdx.x * blockDim.x + threadIdx.x;
    if (e < NEDGES) atomicAdd(&g_cnt[__ldg(&idx_i[e])], 1);
}

__global__ __launch_bounds__(1024) void scan_kernel() {
    __shared__ int s[1024];
    const int T = 1024;
    const int t = threadIdx.x;
    const int CH = (NATOMS + T - 1) / T;
    const int base = t * CH;

    int sum = 0;
    for (int k = 0; k < CH; k++) {
        int idx = base + k;
        if (idx < NATOMS) sum += g_cnt[idx];
    }
    s[t] = sum;
    __syncthreads();
    for (int off = 1; off < T; off <<= 1) {
        int add = (t >= off) ? s[t - off] : 0;
        __syncthreads();
        s[t] += add;
        __syncthreads();
    }
    int run = s[t] - sum;
    for (int k = 0; k < CH; k++) {
        int idx = base + k;
        if (idx < NATOMS) { g_off[idx] = run; run += g_cnt[idx]; }
    }
}

__global__ __launch_bounds__(256) void scatter_kernel(
    const int* __restrict__ idx_i, const int* __restrict__ idx_j)
{
    int e = blockIdx.x * blockDim.x + threadIdx.x;
    if (e < NEDGES) {
        int i = __ldg(&idx_i[e]);
        int pos = g_off[i] + atomicAdd(&g_cur[i], 1);
        g_ej[pos] = make_int2(e, __ldg(&idx_j[e]));
    }
}

// ---------------------------------------------------------------------------
// Kernel C: CSR accumulation — one warp per atom i, zero atomics.
// Lane l owns features {2l, 2l+1}. Per edge: 9 coalesced float2 loads.
// Final: out = concat(q,mu) + accumulated delta (single coalesced store).
// ---------------------------------------------------------------------------
__global__ __launch_bounds__(256) void painn_csr_kernel(
    const float* __restrict__ Wij, const float* __restrict__ dir_ij,
    const float* __restrict__ mu,  const float* __restrict__ x,
    const float* __restrict__ q,   float* __restrict__ out)
{
    const int warp = (blockIdx.x * blockDim.x + threadIdx.x) >> 5;
    const int lane = threadIdx.x & 31;
    if (warp >= NATOMS) return;
    const int i = warp;

    const int beg = g_off[i];
    const int end = beg + g_cnt[i];

    float aqx = 0.f, aqy = 0.f;
    float a0x = 0.f, a0y = 0.f;
    float a1x = 0.f, a1y = 0.f;
    float a2x = 0.f, a2y = 0.f;

    for (int p = beg; p < end; p++) {
        const int2 ej = __ldg(&g_ej[p]);      // broadcast across warp
        const int e = ej.x, j = ej.y;

        const float2* W2p = (const float2*)(Wij + (size_t)e * 192);
        const float2* X2p = (const float2*)(x   + (size_t)j * 192);
        const float2* M2p = (const float2*)(mu  + (size_t)j * 192);

        const float2 w0 = __ldg(&W2p[lane]);
        const float2 w1 = __ldg(&W2p[32 + lane]);
        const float2 w2 = __ldg(&W2p[64 + lane]);
        const float2 x0 = __ldg(&X2p[lane]);
        const float2 x1 = __ldg(&X2p[32 + lane]);
        const float2 x2 = __ldg(&X2p[64 + lane]);
        const float2 m0 = __ldg(&M2p[lane]);
        const float2 m1 = __ldg(&M2p[32 + lane]);
        const float2 m2 = __ldg(&M2p[64 + lane]);

        const float dx = __ldg(&dir_ij[(size_t)e * 3 + 0]);
        const float dy = __ldg(&dir_ij[(size_t)e * 3 + 1]);
        const float dz = __ldg(&dir_ij[(size_t)e * 3 + 2]);

        // dq
        aqx = fmaf(w0.x, x0.x, aqx);
        aqy = fmaf(w0.y, x0.y, aqy);
        // dmuR / dmumu
        const float mRx = w1.x * x1.x, mRy = w1.y * x1.y;
        const float mMx = w2.x * x2.x, mMy = w2.y * x2.y;

        a0x = fmaf(mRx, dx, fmaf(mMx, m0.x, a0x));
        a0y = fmaf(mRy, dx, fmaf(mMy, m0.y, a0y));
        a1x = fmaf(mRx, dy, fmaf(mMx, m1.x, a1x));
        a1y = fmaf(mRy, dy, fmaf(mMy, m1.y, a1y));
        a2x = fmaf(mRx, dz, fmaf(mMx, m2.x, a2x));
        a2y = fmaf(mRy, dz, fmaf(mMy, m2.y, a2y));
    }

    // out_q = q + dq
    {
        const float2 qb = __ldg((const float2*)(q + (size_t)i * 64) + lane);
        float2 o; o.x = qb.x + aqx; o.y = qb.y + aqy;
        *((float2*)(out + (size_t)i * 64) + lane) = o;
    }
    // out_mu = mu + dmu
    {
        const float2* mb = (const float2*)(mu + (size_t)i * 192);
        float2* ob = (float2*)(out + (size_t)NATOMS * 64 + (size_t)i * 192);
        float2 b0 = __ldg(&mb[lane]);
        float2 b1 = __ldg(&mb[32 + lane]);
        float2 b2 = __ldg(&mb[64 + lane]);
        float2 o0, o1, o2;
        o0.x = b0.x + a0x; o0.y = b0.y + a0y;
        o1.x = b1.x + a1x; o1.y = b1.y + a1y;
        o2.x = b2.x + a2x; o2.y = b2.y + a2y;
        ob[lane] = o0;
        ob[32 + lane] = o1;
        ob[64 + lane] = o2;
    }
}

// ---------------------------------------------------------------------------
// launch
// ---------------------------------------------------------------------------
extern "C" void kernel_launch(void* const* d_in, const int* in_sizes, int n_in,
                              void* d_out, int out_size)
{
    int iq = -1, imu = -1, iW = -1, idir = -1, ii = -1, ij = -1;
    int iW1 = -1, ib1 = -1, iW2 = -1, ib2 = -1;
    for (int k = 0; k < n_in; k++) {
        long s = in_sizes[k];
        if      (s == (long)NATOMS * 64)   iq  = k;
        else if (s == (long)NATOMS * 192)  imu = k;
        else if (s == (long)NEDGES * 192)  iW  = k;
        else if (s == (long)NEDGES * 3)    idir = k;
        else if (s == (long)NEDGES)        { if (ii < 0) ii = k; else ij = k; }
        else if (s == 64 * 64)             iW1 = k;
        else if (s == 64)                  ib1 = k;
        else if (s == 64 * 192)            iW2 = k;
        else if (s == 192)                 ib2 = k;
    }

    const float* q   = (const float*)d_in[iq];
    const float* mu  = (const float*)d_in[imu];
    const float* Wij = (const float*)d_in[iW];
    const float* dir = (const float*)d_in[idir];
    const int*  idxi = (const int*)d_in[ii];
    const int*  idxj = (const int*)d_in[ij];
    const float* W1  = (const float*)d_in[iW1];
    const float* b1  = (const float*)d_in[ib1];
    const float* W2  = (const float*)d_in[iW2];
    const float* b2  = (const float*)d_in[ib2];
    float* out = (float*)d_out;

    float* xbuf;
    cudaGetSymbolAddress((void**)&xbuf, g_x);

    // prep: CSR by idx_i
    zero_cnt_kernel<<<(NATOMS + 255) / 256, 256>>>();
    hist_kernel<<<(NEDGES + 255) / 256, 256>>>(idxi);
    scan_kernel<<<1, 1024>>>();
    scatter_kernel<<<(NEDGES + 255) / 256, 256>>>(idxi, idxj);

    // per-atom MLP -> g_x
    painn_mlp_kernel<<<(NATOMS + 127) / 128, 256>>>(q, W1, b1, W2, b2, xbuf);

    // CSR accumulate + base add (one warp per atom)
    {
        const int warps_per_block = 256 / 32;
        const int blocks = (NATOMS + warps_per_block - 1) / warps_per_block;
        painn_csr_kernel<<<blocks, 256>>>(Wij, dir, mu, xbuf, q, out);
    }
}

// round 5
// speedup vs baseline: 1.0846x; 1.0846x over previous
#include <cuda_runtime.h>
#include <cuda_fp16.h>
#include <cstdint>

#define NATOMS 50000
#define NEDGES 800000
#define NWARPS_EDGE (NEDGES / 16)   // 50000, 16 edges per warp

// scratch
__device__ __half2 g_xh[NATOMS * 96];    // x = MLP(q) in fp16, [N,192]
__device__ __half2 g_muh[NATOMS * 96];   // mu in fp16, [N,192]
__device__ int     g_cnt[NATOMS];
__device__ int     g_off[NATOMS];
__device__ int     g_cur[NATOMS];
__device__ int     g_se[NEDGES];         // edge ids sorted by idx_i
__device__ unsigned g_sji[NEDGES];       // (j<<16)|i, sorted by idx_i

// ---- packed f32x2 helpers -------------------------------------------------
#define PK2(d, lo, hi) \
    asm("mov.b64 %0, {%1, %2};" : "=l"(d) : "r"(__float_as_uint(lo)), "r"(__float_as_uint(hi)))
#define UPK2(lo, hi, d) do { unsigned _ulo, _uhi; \
    asm("mov.b64 {%0, %1}, %2;" : "=r"(_ulo), "=r"(_uhi) : "l"(d)); \
    lo = __uint_as_float(_ulo); hi = __uint_as_float(_uhi); } while (0)
#define FMA2(acc, a, b) \
    asm("fma.rn.f32x2 %0, %1, %2, %0;" : "+l"(acc) : "l"(a), "l"(b))

#define HSTRIDE 68

// ---------------------------------------------------------------------------
// Kernel A: per-atom MLP  x = W2 * silu(W1*q + b1) + b2   (output in fp16)
// ---------------------------------------------------------------------------
__global__ __launch_bounds__(256) void painn_mlp_kernel(
    const float* __restrict__ q,
    const float* __restrict__ W1, const float* __restrict__ b1,
    const float* __restrict__ W2, const float* __restrict__ b2,
    __half2* __restrict__ xh)
{
    __shared__ float sH[128 * HSTRIDE];
    __shared__ float sB2[192];

    const int t = threadIdx.x;
    const int atom0 = blockIdx.x * 128;
    const int tx = t & 15;
    const int ty = t >> 4;

    for (int k = t; k < 128 * 16; k += 256) {
        int a = k >> 4, c4 = k & 15;
        int ga = atom0 + a;
        float4 v = (ga < NATOMS) ? __ldg((const float4*)q + (size_t)ga * 16 + c4)
                                 : make_float4(0.f, 0.f, 0.f, 0.f);
        *(float4*)&sH[a * HSTRIDE + c4 * 4] = v;
    }
    if (t < 192) sB2[t] = b2[t];
    __syncthreads();

    // phase 1: h = silu(q*W1 + b1)
    unsigned long long acc1[8][2];
#pragma unroll
    for (int r = 0; r < 8; r++) { acc1[r][0] = 0ull; acc1[r][1] = 0ull; }

    const float4* W1v = (const float4*)W1;
#pragma unroll 4
    for (int k = 0; k < 64; k++) {
        float4 w = __ldg(&W1v[k * 16 + tx]);
        unsigned long long wp0, wp1;
        PK2(wp0, w.x, w.y);
        PK2(wp1, w.z, w.w);
#pragma unroll
        for (int r = 0; r < 8; r++) {
            float h = sH[(ty * 8 + r) * HSTRIDE + k];
            unsigned long long hp;
            PK2(hp, h, h);
            FMA2(acc1[r][0], hp, wp0);
            FMA2(acc1[r][1], hp, wp1);
        }
    }
    __syncthreads();

    {
        float b0 = __ldg(&b1[tx * 4 + 0]);
        float bb1 = __ldg(&b1[tx * 4 + 1]);
        float b2v = __ldg(&b1[tx * 4 + 2]);
        float b3 = __ldg(&b1[tx * 4 + 3]);
#pragma unroll
        for (int r = 0; r < 8; r++) {
            float v0, v1, v2, v3;
            UPK2(v0, v1, acc1[r][0]);
            UPK2(v2, v3, acc1[r][1]);
            v0 += b0; v1 += bb1; v2 += b2v; v3 += b3;
            v0 = v0 / (1.0f + __expf(-v0));
            v1 = v1 / (1.0f + __expf(-v1));
            v2 = v2 / (1.0f + __expf(-v2));
            v3 = v3 / (1.0f + __expf(-v3));
            float* row = &sH[(ty * 8 + r) * HSTRIDE + tx * 4];
            row[0] = v0; row[1] = v1; row[2] = v2; row[3] = v3;
        }
    }
    __syncthreads();

    // phase 2: x = h*W2 + b2
    unsigned long long a2[8][6];
#pragma unroll
    for (int r = 0; r < 8; r++)
#pragma unroll
        for (int c = 0; c < 6; c++) a2[r][c] = 0ull;

    const float4* W2v = (const float4*)W2;
    const int oc4 = tx * 3;
#pragma unroll 2
    for (int k = 0; k < 64; k++) {
        float4 wa = __ldg(&W2v[k * 48 + oc4 + 0]);
        float4 wb = __ldg(&W2v[k * 48 + oc4 + 1]);
        float4 wc = __ldg(&W2v[k * 48 + oc4 + 2]);
        unsigned long long w0, w1, w2, w3, w4, w5;
        PK2(w0, wa.x, wa.y); PK2(w1, wa.z, wa.w);
        PK2(w2, wb.x, wb.y); PK2(w3, wb.z, wb.w);
        PK2(w4, wc.x, wc.y); PK2(w5, wc.z, wc.w);
#pragma unroll
        for (int r = 0; r < 8; r++) {
            float h = sH[(ty * 8 + r) * HSTRIDE + k];
            unsigned long long hp;
            PK2(hp, h, h);
            FMA2(a2[r][0], hp, w0);
            FMA2(a2[r][1], hp, w1);
            FMA2(a2[r][2], hp, w2);
            FMA2(a2[r][3], hp, w3);
            FMA2(a2[r][4], hp, w4);
            FMA2(a2[r][5], hp, w5);
        }
    }

    const int ocol = tx * 12;
#pragma unroll
    for (int r = 0; r < 8; r++) {
        int atom = atom0 + ty * 8 + r;
        if (atom < NATOMS) {
            float v[12];
#pragma unroll
            for (int c = 0; c < 6; c++) UPK2(v[2 * c], v[2 * c + 1], a2[r][c]);
            __half2* dst = &xh[(size_t)atom * 96 + tx * 6];
#pragma unroll
            for (int c = 0; c < 6; c++) {
                dst[c] = __floats2half2_rn(v[2 * c] + sB2[ocol + 2 * c],
                                           v[2 * c + 1] + sB2[ocol + 2 * c + 1]);
            }
        }
    }
}

// ---------------------------------------------------------------------------
// Kernel: convert mu (fp32) -> g_muh (fp16)
// ---------------------------------------------------------------------------
__global__ __launch_bounds__(256) void mu_convert_kernel(const float* __restrict__ mu) {
    const int n2 = NATOMS * 96;   // half2 count
    int i = blockIdx.x * blockDim.x + threadIdx.x;
    if (i < n2) {
        float2 v = __ldg((const float2*)mu + i);
        g_muh[i] = __floats2half2_rn(v.x, v.y);
    }
}

// ---------------------------------------------------------------------------
// Kernel B: out = concat(q, mu)
// ---------------------------------------------------------------------------
__global__ __launch_bounds__(256) void painn_init_out_kernel(
    const float* __restrict__ q, const float* __restrict__ mu,
    float* __restrict__ out)
{
    const size_t NQ4 = (size_t)NATOMS * 64 / 4;
    const size_t NT4 = (size_t)NATOMS * 256 / 4;
    size_t i = (size_t)blockIdx.x * blockDim.x + threadIdx.x;
    if (i < NQ4) {
        ((float4*)out)[i] = ((const float4*)q)[i];
    } else if (i < NT4) {
        ((float4*)out)[i] = ((const float4*)mu)[i - NQ4];
    }
}

// ---------------------------------------------------------------------------
// Sort-by-i prep
// ---------------------------------------------------------------------------
__global__ __launch_bounds__(256) void zero_cnt_kernel() {
    int i = blockIdx.x * blockDim.x + threadIdx.x;
    if (i < NATOMS) { g_cnt[i] = 0; g_cur[i] = 0; }
}

__global__ __launch_bounds__(256) void hist_kernel(const int* __restrict__ idx_i) {
    int e = blockIdx.x * blockDim.x + threadIdx.x;
    if (e < NEDGES) atomicAdd(&g_cnt[__ldg(&idx_i[e])], 1);
}

__global__ __launch_bounds__(1024) void scan_kernel() {
    __shared__ int s[1024];
    const int T = 1024;
    const int t = threadIdx.x;
    const int CH = (NATOMS + T - 1) / T;
    const int base = t * CH;

    int sum = 0;
    for (int k = 0; k < CH; k++) {
        int idx = base + k;
        if (idx < NATOMS) sum += g_cnt[idx];
    }
    s[t] = sum;
    __syncthreads();
    for (int off = 1; off < T; off <<= 1) {
        int add = (t >= off) ? s[t - off] : 0;
        __syncthreads();
        s[t] += add;
        __syncthreads();
    }
    int run = s[t] - sum;
    for (int k = 0; k < CH; k++) {
        int idx = base + k;
        if (idx < NATOMS) { g_off[idx] = run; run += g_cnt[idx]; }
    }
}

__global__ __launch_bounds__(256) void scatter_kernel(
    const int* __restrict__ idx_i, const int* __restrict__ idx_j)
{
    int e = blockIdx.x * blockDim.x + threadIdx.x;
    if (e < NEDGES) {
        int i = __ldg(&idx_i[e]);
        int j = __ldg(&idx_j[e]);
        int pos = g_off[i] + atomicAdd(&g_cur[i], 1);
        g_se[pos]  = e;
        g_sji[pos] = ((unsigned)j << 16) | (unsigned)i;
    }
}

// ---------------------------------------------------------------------------
// Kernel C: segmented edge reduction. 16 i-sorted edges per warp.
// Lane l owns features {2l, 2l+1}. Register accumulation within i-runs,
// red.global.add.v2.f32 flush at segment boundaries.
// ---------------------------------------------------------------------------
__device__ __forceinline__ void red2(float* p, float a, float b) {
    asm volatile("red.global.add.v2.f32 [%0], {%1, %2};"
                 :: "l"(p), "f"(a), "f"(b) : "memory");
}

__global__ __launch_bounds__(256) void painn_edge_kernel(
    const float* __restrict__ Wij, const float* __restrict__ dir_ij,
    float* __restrict__ out)
{
    const int warp = (blockIdx.x * blockDim.x + threadIdx.x) >> 5;
    const int lane = threadIdx.x & 31;
    if (warp >= NWARPS_EDGE) return;

    const int p0 = warp * 16;
    const int p1 = p0 + 16;   // NEDGES divisible by 16

    int cur_i = (int)(__ldg(&g_sji[p0]) & 0xFFFFu);

    float aqx = 0.f, aqy = 0.f;
    float a0x = 0.f, a0y = 0.f;
    float a1x = 0.f, a1y = 0.f;
    float a2x = 0.f, a2y = 0.f;

    for (int p = p0; p < p1; p++) {
        const unsigned ji = __ldg(&g_sji[p]);
        const int e = __ldg(&g_se[p]);
        const int ii = (int)(ji & 0xFFFFu);
        const int j  = (int)(ji >> 16);

        if (ii != cur_i) {
            // flush segment
            red2(out + (size_t)cur_i * 64 + lane * 2, aqx, aqy);
            float* om = out + (size_t)NATOMS * 64 + (size_t)cur_i * 192 + lane * 2;
            red2(om,       a0x, a0y);
            red2(om + 64,  a1x, a1y);
            red2(om + 128, a2x, a2y);
            aqx = aqy = a0x = a0y = a1x = a1y = a2x = a2y = 0.f;
            cur_i = ii;
        }

        const float2* W2p = (const float2*)(Wij + (size_t)e * 192);
        const __half2* X = g_xh  + (size_t)j * 96;
        const __half2* M = g_muh + (size_t)j * 96;

        const float2 w0 = __ldg(&W2p[lane]);
        const float2 w1 = __ldg(&W2p[32 + lane]);
        const float2 w2 = __ldg(&W2p[64 + lane]);
        const float2 x0 = __half22float2(__ldg(&X[lane]));
        const float2 x1 = __half22float2(__ldg(&X[32 + lane]));
        const float2 x2 = __half22float2(__ldg(&X[64 + lane]));
        const float2 m0 = __half22float2(__ldg(&M[lane]));
        const float2 m1 = __half22float2(__ldg(&M[32 + lane]));
        const float2 m2 = __half22float2(__ldg(&M[64 + lane]));

        const float dx = __ldg(&dir_ij[(size_t)e * 3 + 0]);
        const float dy = __ldg(&dir_ij[(size_t)e * 3 + 1]);
        const float dz = __ldg(&dir_ij[(size_t)e * 3 + 2]);

        aqx = fmaf(w0.x, x0.x, aqx);
        aqy = fmaf(w0.y, x0.y, aqy);

        const float mRx = w1.x * x1.x, mRy = w1.y * x1.y;
        const float mMx = w2.x * x2.x, mMy = w2.y * x2.y;

        a0x = fmaf(mRx, dx, fmaf(mMx, m0.x, a0x));
        a0y = fmaf(mRy, dx, fmaf(mMy, m0.y, a0y));
        a1x = fmaf(mRx, dy, fmaf(mMx, m1.x, a1x));
        a1y = fmaf(mRy, dy, fmaf(mMy, m1.y, a1y));
        a2x = fmaf(mRx, dz, fmaf(mMx, m2.x, a2x));
        a2y = fmaf(mRy, dz, fmaf(mMy, m2.y, a2y));
    }

    // final flush
    red2(out + (size_t)cur_i * 64 + lane * 2, aqx, aqy);
    float* om = out + (size_t)NATOMS * 64 + (size_t)cur_i * 192 + lane * 2;
    red2(om,       a0x, a0y);
    red2(om + 64,  a1x, a1y);
    red2(om + 128, a2x, a2y);
}

// ---------------------------------------------------------------------------
// launch
// ---------------------------------------------------------------------------
extern "C" void kernel_launch(void* const* d_in, const int* in_sizes, int n_in,
                              void* d_out, int out_size)
{
    int iq = -1, imu = -1, iW = -1, idir = -1, ii = -1, ij = -1;
    int iW1 = -1, ib1 = -1, iW2 = -1, ib2 = -1;
    for (int k = 0; k < n_in; k++) {
        long s = in_sizes[k];
        if      (s == (long)NATOMS * 64)   iq  = k;
        else if (s == (long)NATOMS * 192)  imu = k;
        else if (s == (long)NEDGES * 192)  iW  = k;
        else if (s == (long)NEDGES * 3)    idir = k;
        else if (s == (long)NEDGES)        { if (ii < 0) ii = k; else ij = k; }
        else if (s == 64 * 64)             iW1 = k;
        else if (s == 64)                  ib1 = k;
        else if (s == 64 * 192)            iW2 = k;
        else if (s == 192)                 ib2 = k;
    }

    const float* q   = (const float*)d_in[iq];
    const float* mu  = (const float*)d_in[imu];
    const float* Wij = (const float*)d_in[iW];
    const float* dir = (const float*)d_in[idir];
    const int*  idxi = (const int*)d_in[ii];
    const int*  idxj = (const int*)d_in[ij];
    const float* W1  = (const float*)d_in[iW1];
    const float* b1  = (const float*)d_in[ib1];
    const float* W2  = (const float*)d_in[iW2];
    const float* b2  = (const float*)d_in[ib2];
    float* out = (float*)d_out;

    __half2* xh;
    cudaGetSymbolAddress((void**)&xh, g_xh);

    // prep: sort edges by idx_i
    zero_cnt_kernel<<<(NATOMS + 255) / 256, 256>>>();
    hist_kernel<<<(NEDGES + 255) / 256, 256>>>(idxi);
    scan_kernel<<<1, 1024>>>();
    scatter_kernel<<<(NEDGES + 255) / 256, 256>>>(idxi, idxj);

    // per-atom MLP -> fp16 x table
    painn_mlp_kernel<<<(NATOMS + 127) / 128, 256>>>(q, W1, b1, W2, b2, xh);

    // mu -> fp16 table
    mu_convert_kernel<<<(NATOMS * 96 + 255) / 256, 256>>>(mu);

    // out = concat(q, mu)
    {
        const int total4 = NATOMS * 256 / 4;
        painn_init_out_kernel<<<(total4 + 255) / 256, 256>>>(q, mu, out);
    }

    // segmented edge reduction (16 edges per warp)
    {
        const int warps_per_block = 256 / 32;
        const int blocks = (NWARPS_EDGE + warps_per_block - 1) / warps_per_block;
        painn_edge_kernel<<<blocks, 256>>>(Wij, dir, out);
    }
}

// round 6
// speedup vs baseline: 1.0948x; 1.0094x over previous
#include <cuda_runtime.h>
#include <cuda_fp16.h>
#include <cstdint>

#define NATOMS 50000
#define NEDGES 800000
#define NWARPS_EDGE (NEDGES / 16)   // 16 edges per warp

// scratch
__device__ __half2 g_xm[NATOMS * 192];   // per atom: 96 half2 of x, then 96 half2 of mu
__device__ int     g_cnt[NATOMS];
__device__ int     g_off[NATOMS];
__device__ int     g_cur[NATOMS];
__device__ int2    g_pe[NEDGES];         // (e, (j<<16)|i) sorted by idx_i

// ---- packed f32x2 helpers -------------------------------------------------
#define PK2(d, lo, hi) \
    asm("mov.b64 %0, {%1, %2};" : "=l"(d) : "r"(__float_as_uint(lo)), "r"(__float_as_uint(hi)))
#define UPK2(lo, hi, d) do { unsigned _ulo, _uhi; \
    asm("mov.b64 {%0, %1}, %2;" : "=r"(_ulo), "=r"(_uhi) : "l"(d)); \
    lo = __uint_as_float(_ulo); hi = __uint_as_float(_uhi); } while (0)
#define FMA2(acc, a, b) \
    asm("fma.rn.f32x2 %0, %1, %2, %0;" : "+l"(acc) : "l"(a), "l"(b))

#define HSTRIDE 68

// ---------------------------------------------------------------------------
// Kernel A: per-atom MLP  x = W2 * silu(W1*q + b1) + b2   -> fp16 in g_xm[:,0:96]
// ---------------------------------------------------------------------------
__global__ __launch_bounds__(256) void painn_mlp_kernel(
    const float* __restrict__ q,
    const float* __restrict__ W1, const float* __restrict__ b1,
    const float* __restrict__ W2, const float* __restrict__ b2)
{
    __shared__ float sH[128 * HSTRIDE];
    __shared__ float sB2[192];

    const int t = threadIdx.x;
    const int atom0 = blockIdx.x * 128;
    const int tx = t & 15;
    const int ty = t >> 4;

    for (int k = t; k < 128 * 16; k += 256) {
        int a = k >> 4, c4 = k & 15;
        int ga = atom0 + a;
        float4 v = (ga < NATOMS) ? __ldg((const float4*)q + (size_t)ga * 16 + c4)
                                 : make_float4(0.f, 0.f, 0.f, 0.f);
        *(float4*)&sH[a * HSTRIDE + c4 * 4] = v;
    }
    if (t < 192) sB2[t] = b2[t];
    __syncthreads();

    // phase 1: h = silu(q*W1 + b1)
    unsigned long long acc1[8][2];
#pragma unroll
    for (int r = 0; r < 8; r++) { acc1[r][0] = 0ull; acc1[r][1] = 0ull; }

    const float4* W1v = (const float4*)W1;
#pragma unroll 4
    for (int k = 0; k < 64; k++) {
        float4 w = __ldg(&W1v[k * 16 + tx]);
        unsigned long long wp0, wp1;
        PK2(wp0, w.x, w.y);
        PK2(wp1, w.z, w.w);
#pragma unroll
        for (int r = 0; r < 8; r++) {
            float h = sH[(ty * 8 + r) * HSTRIDE + k];
            unsigned long long hp;
            PK2(hp, h, h);
            FMA2(acc1[r][0], hp, wp0);
            FMA2(acc1[r][1], hp, wp1);
        }
    }
    __syncthreads();

    {
        float b0 = __ldg(&b1[tx * 4 + 0]);
        float bb1 = __ldg(&b1[tx * 4 + 1]);
        float b2v = __ldg(&b1[tx * 4 + 2]);
        float b3 = __ldg(&b1[tx * 4 + 3]);
#pragma unroll
        for (int r = 0; r < 8; r++) {
            float v0, v1, v2, v3;
            UPK2(v0, v1, acc1[r][0]);
            UPK2(v2, v3, acc1[r][1]);
            v0 += b0; v1 += bb1; v2 += b2v; v3 += b3;
            v0 = v0 / (1.0f + __expf(-v0));
            v1 = v1 / (1.0f + __expf(-v1));
            v2 = v2 / (1.0f + __expf(-v2));
            v3 = v3 / (1.0f + __expf(-v3));
            float* row = &sH[(ty * 8 + r) * HSTRIDE + tx * 4];
            row[0] = v0; row[1] = v1; row[2] = v2; row[3] = v3;
        }
    }
    __syncthreads();

    // phase 2: x = h*W2 + b2
    unsigned long long a2[8][6];
#pragma unroll
    for (int r = 0; r < 8; r++)
#pragma unroll
        for (int c = 0; c < 6; c++) a2[r][c] = 0ull;

    const float4* W2v = (const float4*)W2;
    const int oc4 = tx * 3;
#pragma unroll 2
    for (int k = 0; k < 64; k++) {
        float4 wa = __ldg(&W2v[k * 48 + oc4 + 0]);
        float4 wb = __ldg(&W2v[k * 48 + oc4 + 1]);
        float4 wc = __ldg(&W2v[k * 48 + oc4 + 2]);
        unsigned long long w0, w1, w2, w3, w4, w5;
        PK2(w0, wa.x, wa.y); PK2(w1, wa.z, wa.w);
        PK2(w2, wb.x, wb.y); PK2(w3, wb.z, wb.w);
        PK2(w4, wc.x, wc.y); PK2(w5, wc.z, wc.w);
#pragma unroll
        for (int r = 0; r < 8; r++) {
            float h = sH[(ty * 8 + r) * HSTRIDE + k];
            unsigned long long hp;
            PK2(hp, h, h);
            FMA2(a2[r][0], hp, w0);
            FMA2(a2[r][1], hp, w1);
            FMA2(a2[r][2], hp, w2);
            FMA2(a2[r][3], hp, w3);
            FMA2(a2[r][4], hp, w4);
            FMA2(a2[r][5], hp, w5);
        }
    }

    const int ocol = tx * 12;
#pragma unroll
    for (int r = 0; r < 8; r++) {
        int atom = atom0 + ty * 8 + r;
        if (atom < NATOMS) {
            float v[12];
#pragma unroll
            for (int c = 0; c < 6; c++) UPK2(v[2 * c], v[2 * c + 1], a2[r][c]);
            __half2* dst = &g_xm[(size_t)atom * 192 + tx * 6];
#pragma unroll
            for (int c = 0; c < 6; c++) {
                dst[c] = __floats2half2_rn(v[2 * c] + sB2[ocol + 2 * c],
                                           v[2 * c + 1] + sB2[ocol + 2 * c + 1]);
            }
        }
    }
}

// ---------------------------------------------------------------------------
// mu (fp32) -> g_xm[:,96:192] fp16
// ---------------------------------------------------------------------------
__global__ __launch_bounds__(256) void mu_convert_kernel(const float* __restrict__ mu) {
    const int n2 = NATOMS * 96;
    int i = blockIdx.x * blockDim.x + threadIdx.x;
    if (i < n2) {
        float2 v = __ldg((const float2*)mu + i);
        g_xm[(size_t)(i / 96) * 192 + 96 + (i % 96)] = __floats2half2_rn(v.x, v.y);
    }
}

// ---------------------------------------------------------------------------
// out = concat(q, mu)
// ---------------------------------------------------------------------------
__global__ __launch_bounds__(256) void painn_init_out_kernel(
    const float* __restrict__ q, const float* __restrict__ mu,
    float* __restrict__ out)
{
    const size_t NQ4 = (size_t)NATOMS * 64 / 4;
    const size_t NT4 = (size_t)NATOMS * 256 / 4;
    size_t i = (size_t)blockIdx.x * blockDim.x + threadIdx.x;
    if (i < NQ4) {
        ((float4*)out)[i] = ((const float4*)q)[i];
    } else if (i < NT4) {
        ((float4*)out)[i] = ((const float4*)mu)[i - NQ4];
    }
}

// ---------------------------------------------------------------------------
// Sort-by-i prep
// ---------------------------------------------------------------------------
__global__ __launch_bounds__(256) void zero_cnt_kernel() {
    int i = blockIdx.x * blockDim.x + threadIdx.x;
    if (i < NATOMS) { g_cnt[i] = 0; g_cur[i] = 0; }
}

__global__ __launch_bounds__(256) void hist_kernel(const int* __restrict__ idx_i) {
    int e = blockIdx.x * blockDim.x + threadIdx.x;
    if (e < NEDGES) atomicAdd(&g_cnt[__ldg(&idx_i[e])], 1);
}

__global__ __launch_bounds__(1024) void scan_kernel() {
    __shared__ int s[1024];
    const int T = 1024;
    const int t = threadIdx.x;
    const int CH = (NATOMS + T - 1) / T;
    const int base = t * CH;

    int sum = 0;
    for (int k = 0; k < CH; k++) {
        int idx = base + k;
        if (idx < NATOMS) sum += g_cnt[idx];
    }
    s[t] = sum;
    __syncthreads();
    for (int off = 1; off < T; off <<= 1) {
        int add = (t >= off) ? s[t - off] : 0;
        __syncthreads();
        s[t] += add;
        __syncthreads();
    }
    int run = s[t] - sum;
    for (int k = 0; k < CH; k++) {
        int idx = base + k;
        if (idx < NATOMS) { g_off[idx] = run; run += g_cnt[idx]; }
    }
}

__global__ __launch_bounds__(256) void scatter_kernel(
    const int* __restrict__ idx_i, const int* __restrict__ idx_j)
{
    int e = blockIdx.x * blockDim.x + threadIdx.x;
    if (e < NEDGES) {
        int i = __ldg(&idx_i[e]);
        int j = __ldg(&idx_j[e]);
        int pos = g_off[i] + atomicAdd(&g_cur[i], 1);
        g_pe[pos] = make_int2(e, (j << 16) | i);
    }
}

// ---------------------------------------------------------------------------
// Kernel C: segmented edge reduction, 16 i-sorted edges/warp,
// unrolled 4-edge batches with register-resident indices (high MLP).
// ---------------------------------------------------------------------------
__device__ __forceinline__ void red2(float* p, float a, float b) {
    asm volatile("red.global.add.v2.f32 [%0], {%1, %2};"
                 :: "l"(p), "f"(a), "f"(b) : "memory");
}

__global__ __launch_bounds__(256) void painn_edge_kernel(
    const float* __restrict__ Wij, const float* __restrict__ dir_ij,
    float* __restrict__ out)
{
    const int warp = (blockIdx.x * blockDim.x + threadIdx.x) >> 5;
    const int lane = threadIdx.x & 31;
    if (warp >= NWARPS_EDGE) return;

    const int p0 = warp * 16;
    const int4* pe4 = (const int4*)(g_pe + p0);   // 16 int2 = 8 int4

    int4 first = __ldg(&pe4[0]);
    int cur_i = first.y & 0xFFFF;

    float aqx = 0.f, aqy = 0.f;
    float a0x = 0.f, a0y = 0.f;
    float a1x = 0.f, a1y = 0.f;
    float a2x = 0.f, a2y = 0.f;

#define FLUSH() do { \
        red2(out + (size_t)cur_i * 64 + lane * 2, aqx, aqy); \
        float* _om = out + (size_t)NATOMS * 64 + (size_t)cur_i * 192 + lane * 2; \
        red2(_om,       a0x, a0y); \
        red2(_om + 64,  a1x, a1y); \
        red2(_om + 128, a2x, a2y); \
        aqx = aqy = a0x = a0y = a1x = a1y = a2x = a2y = 0.f; \
    } while (0)

#pragma unroll
    for (int b = 0; b < 4; b++) {
        const int4 pa = __ldg(&pe4[2 * b]);
        const int4 pb = __ldg(&pe4[2 * b + 1]);
        const int e_[4]  = {pa.x, pa.z, pb.x, pb.z};
        const int ji_[4] = {pa.y, pa.w, pb.y, pb.w};

#pragma unroll
        for (int u = 0; u < 4; u++) {
            const int e  = e_[u];
            const int ii = ji_[u] & 0xFFFF;
            const int j  = ((unsigned)ji_[u]) >> 16;

            if (ii != cur_i) { FLUSH(); cur_i = ii; }

            const float2* W2p = (const float2*)(Wij + (size_t)e * 192);
            const __half2* T = g_xm + (size_t)j * 192;

            const float2 w0 = __ldg(&W2p[lane]);
            const float2 w1 = __ldg(&W2p[32 + lane]);
            const float2 w2 = __ldg(&W2p[64 + lane]);
            const float2 x0 = __half22float2(__ldg(&T[lane]));
            const float2 x1 = __half22float2(__ldg(&T[32 + lane]));
            const float2 x2 = __half22float2(__ldg(&T[64 + lane]));
            const float2 m0 = __half22float2(__ldg(&T[96 + lane]));
            const float2 m1 = __half22float2(__ldg(&T[128 + lane]));
            const float2 m2 = __half22float2(__ldg(&T[160 + lane]));

            const float dx = __ldg(&dir_ij[(size_t)e * 3 + 0]);
            const float dy = __ldg(&dir_ij[(size_t)e * 3 + 1]);
            const float dz = __ldg(&dir_ij[(size_t)e * 3 + 2]);

            aqx = fmaf(w0.x, x0.x, aqx);
            aqy = fmaf(w0.y, x0.y, aqy);

            const float mRx = w1.x * x1.x, mRy = w1.y * x1.y;
            const float mMx = w2.x * x2.x, mMy = w2.y * x2.y;

            a0x = fmaf(mRx, dx, fmaf(mMx, m0.x, a0x));
            a0y = fmaf(mRy, dx, fmaf(mMy, m0.y, a0y));
            a1x = fmaf(mRx, dy, fmaf(mMx, m1.x, a1x));
            a1y = fmaf(mRy, dy, fmaf(mMy, m1.y, a1y));
            a2x = fmaf(mRx, dz, fmaf(mMx, m2.x, a2x));
            a2y = fmaf(mRy, dz, fmaf(mMy, m2.y, a2y));
        }
    }

    FLUSH();
#undef FLUSH
}

// ---------------------------------------------------------------------------
// launch
// ---------------------------------------------------------------------------
extern "C" void kernel_launch(void* const* d_in, const int* in_sizes, int n_in,
                              void* d_out, int out_size)
{
    int iq = -1, imu = -1, iW = -1, idir = -1, ii = -1, ij = -1;
    int iW1 = -1, ib1 = -1, iW2 = -1, ib2 = -1;
    for (int k = 0; k < n_in; k++) {
        long s = in_sizes[k];
        if      (s == (long)NATOMS * 64)   iq  = k;
        else if (s == (long)NATOMS * 192)  imu = k;
        else if (s == (long)NEDGES * 192)  iW  = k;
        else if (s == (long)NEDGES * 3)    idir = k;
        else if (s == (long)NEDGES)        { if (ii < 0) ii = k; else ij = k; }
        else if (s == 64 * 64)             iW1 = k;
        else if (s == 64)                  ib1 = k;
        else if (s == 64 * 192)            iW2 = k;
        else if (s == 192)                 ib2 = k;
    }

    const float* q   = (const float*)d_in[iq];
    const float* mu  = (const float*)d_in[imu];
    const float* Wij = (const float*)d_in[iW];
    const float* dir = (const float*)d_in[idir];
    const int*  idxi = (const int*)d_in[ii];
    const int*  idxj = (const int*)d_in[ij];
    const float* W1  = (const float*)d_in[iW1];
    const float* b1  = (const float*)d_in[ib1];
    const float* W2  = (const float*)d_in[iW2];
    const float* b2  = (const float*)d_in[ib2];
    float* out = (float*)d_out;

    // prep: sort edges by idx_i
    zero_cnt_kernel<<<(NATOMS + 255) / 256, 256>>>();
    hist_kernel<<<(NEDGES + 255) / 256, 256>>>(idxi);
    scan_kernel<<<1, 1024>>>();
    scatter_kernel<<<(NEDGES + 255) / 256, 256>>>(idxi, idxj);

    // per-atom MLP -> fp16 x part of g_xm
    painn_mlp_kernel<<<(NATOMS + 127) / 128, 256>>>(q, W1, b1, W2, b2);

    // mu -> fp16 part of g_xm
    mu_convert_kernel<<<(NATOMS * 96 + 255) / 256, 256>>>(mu);

    // out = concat(q, mu)
    {
        const int total4 = NATOMS * 256 / 4;
        painn_init_out_kernel<<<(total4 + 255) / 256, 256>>>(q, mu, out);
    }

    // segmented edge reduction
    {
        const int warps_per_block = 256 / 32;
        const int blocks = (NWARPS_EDGE + warps_per_block - 1) / warps_per_block;
        painn_edge_kernel<<<blocks, 256>>>(Wij, dir, out);
    }
}